// round 10
// baseline (speedup 1.0000x reference)
#include <cuda_runtime.h>
#include <cstdint>
#include <math.h>

#define B_  4
#define S_  2048
#define D_  1024
#define H_  16
#define DH_ 64
#define MROWS (B_ * S_)
#define VPAD 68

typedef unsigned long long ull;

__device__ __forceinline__ ull pk2(float a, float b) {
    ull r; asm("mov.b64 %0, {%1, %2};" : "=l"(r) : "f"(a), "f"(b)); return r;
}
__device__ __forceinline__ float2 up2(ull v) {
    float2 r; asm("mov.b64 {%0, %1}, %2;" : "=f"(r.x), "=f"(r.y) : "l"(v)); return r;
}
__device__ __forceinline__ ull f2fma(ull a, ull b, ull c) {
    ull d; asm("fma.rn.f32x2 %0, %1, %2, %3;" : "=l"(d) : "l"(a), "l"(b), "l"(c)); return d;
}
__device__ __forceinline__ ull f2mul(ull a, ull b) {
    ull d; asm("mul.rn.f32x2 %0, %1, %2;" : "=l"(d) : "l"(a), "l"(b)); return d;
}

__device__ float g_q[MROWS * D_];
__device__ float g_k[MROWS * D_];
__device__ float g_v[MROWS * D_];
__device__ float g_o[MROWS * D_];

// ---------------------------------------------------------------------------
// GEMM v3: C[8192,1024] = A * W^T.  128x128 tile, BK=16, 256 threads,
// 8x8 per thread with SPLIT fragments (4+4 at distance 64) -> conflict-free
// B reads; A duplicated in smem as f32x2 pairs (no per-k pack MOVs);
// double-buffered smem stages + register prefetch (one barrier per tile).
// blockIdx.z picks one of up to 3 independent GEMMs.
// ---------------------------------------------------------------------------
__global__ __launch_bounds__(256, 2) void gemm128(
    const float* __restrict__ A0, const float* __restrict__ A1, const float* __restrict__ A2,
    const float* __restrict__ W0, const float* __restrict__ W1, const float* __restrict__ W2,
    float* __restrict__ C0, float* __restrict__ C1, float* __restrict__ C2)
{
    const float* A; const float* W; float* C;
    if (blockIdx.z == 0)      { A = A0; W = W0; C = C0; }
    else if (blockIdx.z == 1) { A = A1; W = W1; C = C1; }
    else                      { A = A2; W = W2; C = C2; }

    __shared__ __align__(16) ull   As2[2][16][128];   // dup pairs, 32 KB
    __shared__ __align__(16) float Bsf[2][16][128];   // 16 KB

    const int tid = threadIdx.x;
    const int mq  = tid >> 4;            // 0..15
    const int nq  = tid & 15;            // 0..15
    const size_t mBase = (size_t)blockIdx.y * 128;
    const size_t nBase = (size_t)blockIdx.x * 128;

    // loader mapping: row = tid>>1 (0..127), kq = (tid&1)*8
    const int lrow = tid >> 1;
    const int lkq  = (tid & 1) << 3;

    const float* aG = A + (mBase + lrow) * D_ + lkq;
    const float* wG = W + (nBase + lrow) * D_ + lkq;

    float4 pa0, pa1, pb0, pb1;
    pa0 = *(const float4*)aG;       pa1 = *(const float4*)(aG + 4);
    pb0 = *(const float4*)wG;       pb1 = *(const float4*)(wG + 4);

    ull acc[8][4];
#pragma unroll
    for (int i = 0; i < 8; i++)
#pragma unroll
        for (int j = 0; j < 4; j++) acc[i][j] = 0ULL;

    // store tile0 -> stage 0
#define STORE_STAGE(s)                                                        \
    {                                                                         \
        As2[s][lkq + 0][lrow] = pk2(pa0.x, pa0.x);                            \
        As2[s][lkq + 1][lrow] = pk2(pa0.y, pa0.y);                            \
        As2[s][lkq + 2][lrow] = pk2(pa0.z, pa0.z);                            \
        As2[s][lkq + 3][lrow] = pk2(pa0.w, pa0.w);                            \
        As2[s][lkq + 4][lrow] = pk2(pa1.x, pa1.x);                            \
        As2[s][lkq + 5][lrow] = pk2(pa1.y, pa1.y);                            \
        As2[s][lkq + 6][lrow] = pk2(pa1.z, pa1.z);                            \
        As2[s][lkq + 7][lrow] = pk2(pa1.w, pa1.w);                            \
        Bsf[s][lkq + 0][lrow] = pb0.x;  Bsf[s][lkq + 1][lrow] = pb0.y;        \
        Bsf[s][lkq + 2][lrow] = pb0.z;  Bsf[s][lkq + 3][lrow] = pb0.w;        \
        Bsf[s][lkq + 4][lrow] = pb1.x;  Bsf[s][lkq + 5][lrow] = pb1.y;        \
        Bsf[s][lkq + 6][lrow] = pb1.z;  Bsf[s][lkq + 7][lrow] = pb1.w;        \
    }

    STORE_STAGE(0);
    // prefetch tile1 into regs
    aG += 16; wG += 16;
    pa0 = *(const float4*)aG;       pa1 = *(const float4*)(aG + 4);
    pb0 = *(const float4*)wG;       pb1 = *(const float4*)(wG + 4);
    __syncthreads();

    const int NT = D_ / 16;              // 64 tiles
    for (int t = 0; t < NT; t++) {
        const int cur = t & 1;
#pragma unroll
        for (int k = 0; k < 16; k++) {
            // A fragment: dup pairs, broadcast reads (4 x LDS.128)
            ulonglong2 a01 = *(const ulonglong2*)&As2[cur][k][4 * mq];
            ulonglong2 a23 = *(const ulonglong2*)&As2[cur][k][4 * mq + 2];
            ulonglong2 a45 = *(const ulonglong2*)&As2[cur][k][64 + 4 * mq];
            ulonglong2 a67 = *(const ulonglong2*)&As2[cur][k][64 + 4 * mq + 2];
            // B fragment: natural pairs, split chunks (2 x LDS.128, 2-wf each)
            ulonglong2 b01 = *(const ulonglong2*)&Bsf[cur][k][4 * nq];
            ulonglong2 b23 = *(const ulonglong2*)&Bsf[cur][k][64 + 4 * nq];
            ull af[8] = {a01.x, a01.y, a23.x, a23.y, a45.x, a45.y, a67.x, a67.y};
#pragma unroll
            for (int i = 0; i < 8; i++) {
                acc[i][0] = f2fma(af[i], b01.x, acc[i][0]);
                acc[i][1] = f2fma(af[i], b01.y, acc[i][1]);
                acc[i][2] = f2fma(af[i], b23.x, acc[i][2]);
                acc[i][3] = f2fma(af[i], b23.y, acc[i][3]);
            }
        }
        if (t < NT - 1) {
            STORE_STAGE(cur ^ 1);
            if (t < NT - 2) {
                aG += 16; wG += 16;
                pa0 = *(const float4*)aG;   pa1 = *(const float4*)(aG + 4);
                pb0 = *(const float4*)wG;   pb1 = *(const float4*)(wG + 4);
            }
        }
        __syncthreads();
    }
#undef STORE_STAGE

    // epilogue: row m = (i<4 ? 4mq+i : 64+4mq+i-4); cols {4nq..}, {64+4nq..}
#pragma unroll
    for (int i = 0; i < 8; i++) {
        int m = (i < 4) ? (4 * mq + i) : (64 + 4 * mq + (i - 4));
        float2 c0 = up2(acc[i][0]), c1 = up2(acc[i][1]);
        float2 c2 = up2(acc[i][2]), c3 = up2(acc[i][3]);
        float* cp = C + (mBase + m) * D_ + nBase;
        *(float4*)(cp + 4 * nq)      = make_float4(c0.x, c0.y, c1.x, c1.y);
        *(float4*)(cp + 64 + 4 * nq) = make_float4(c2.x, c2.y, c3.x, c3.y);
    }
}

// ---------------------------------------------------------------------------
// Flash v2 (unchanged from R9): 256 threads, 4q x 8k tile, shfl softmax.
// ---------------------------------------------------------------------------
__global__ __launch_bounds__(256, 2) void flash_v2(
    const float* __restrict__ Qp, const float* __restrict__ Kp,
    const float* __restrict__ Vp, float* __restrict__ Op)
{
    extern __shared__ __align__(16) char smr[];
    float* Qs = (float*)smr;            // 64*128
    float* Ks = Qs + 64 * 128;          // 64*64
    float* Vs = Ks + 64 * 64;           // 64*VPAD

    const int tid = threadIdx.x;
    const int n0  = (tid & 7) << 3;
    const int m0  = (tid >> 3) << 2;
    const int bx  = gridDim.x - 1 - blockIdx.x;
    const int qBase = bx * 128;
    const int b = blockIdx.y >> 4, h = blockIdx.y & 15;
    const size_t headOff = (size_t)b * S_ * D_ + (size_t)h * DH_;

    {
        int qr = tid >> 1, dh = (tid & 1) * 32;
        const float* qs = Qp + headOff + (size_t)(qBase + qr) * D_ + dh;
#pragma unroll
        for (int c = 0; c < 8; c++) {
            float4 v = *(const float4*)(qs + 4 * c);
            Qs[(dh + 4*c + 0) * 128 + qr] = v.x * 0.125f;
            Qs[(dh + 4*c + 1) * 128 + qr] = v.y * 0.125f;
            Qs[(dh + 4*c + 2) * 128 + qr] = v.z * 0.125f;
            Qs[(dh + 4*c + 3) * 128 + qr] = v.w * 0.125f;
        }
    }

    ull o[4][4];
#pragma unroll
    for (int i = 0; i < 4; i++)
#pragma unroll
        for (int j = 0; j < 4; j++) o[i][j] = 0ULL;
    float mrow[4] = {-INFINITY, -INFINITY, -INFINITY, -INFINITY};
    float lrow[4] = {0.f, 0.f, 0.f, 0.f};

    const int kr = tid >> 2, dq = (tid & 3) << 4;
    const int nkt = 2 * bx + 2;

    for (int kt = 0; kt < nkt; kt++) {
        const float* kp = Kp + headOff + (size_t)(kt * 64 + kr) * D_ + dq;
        const float* vp = Vp + headOff + (size_t)(kt * 64 + kr) * D_ + dq;
        float4 kv[4], vv[4];
#pragma unroll
        for (int c = 0; c < 4; c++) { kv[c] = *(const float4*)(kp + 4*c); vv[c] = *(const float4*)(vp + 4*c); }
        __syncthreads();
#pragma unroll
        for (int c = 0; c < 4; c++) {
            Ks[(dq + 4*c + 0) * 64 + kr] = kv[c].x;
            Ks[(dq + 4*c + 1) * 64 + kr] = kv[c].y;
            Ks[(dq + 4*c + 2) * 64 + kr] = kv[c].z;
            Ks[(dq + 4*c + 3) * 64 + kr] = kv[c].w;
            *(float4*)&Vs[kr * VPAD + dq + 4*c] = vv[c];
        }
        __syncthreads();

        ull s2[4][4];
#pragma unroll
        for (int i = 0; i < 4; i++)
#pragma unroll
            for (int j = 0; j < 4; j++) s2[i][j] = 0ULL;
        for (int d8 = 0; d8 < 8; d8++) {
#pragma unroll
            for (int dd = 0; dd < 8; dd++) {
                const int d = d8 * 8 + dd;
                float4 qv = *(const float4*)&Qs[d * 128 + m0];
                ulonglong2 k01 = *(const ulonglong2*)&Ks[d * 64 + n0];
                ulonglong2 k23 = *(const ulonglong2*)&Ks[d * 64 + n0 + 4];
                float qa[4] = {qv.x, qv.y, qv.z, qv.w};
#pragma unroll
                for (int i = 0; i < 4; i++) {
                    ull q2 = pk2(qa[i], qa[i]);
                    s2[i][0] = f2fma(q2, k01.x, s2[i][0]);
                    s2[i][1] = f2fma(q2, k01.y, s2[i][1]);
                    s2[i][2] = f2fma(q2, k23.x, s2[i][2]);
                    s2[i][3] = f2fma(q2, k23.y, s2[i][3]);
                }
            }
        }

        float sv[4][8];
        const bool bnd = (kt >= nkt - 2);
        const int kOff = kt * 64 + n0;
#pragma unroll
        for (int i = 0; i < 4; i++) {
#pragma unroll
            for (int j2 = 0; j2 < 4; j2++) {
                float2 u = up2(s2[i][j2]);
                sv[i][2*j2] = u.x; sv[i][2*j2+1] = u.y;
            }
            if (bnd) {
                int q = qBase + m0 + i;
#pragma unroll
                for (int j = 0; j < 8; j++)
                    if (kOff + j > q) sv[i][j] = -INFINITY;
            }
            float mx = sv[i][0];
#pragma unroll
            for (int j = 1; j < 8; j++) mx = fmaxf(mx, sv[i][j]);
            mx = fmaxf(mx, __shfl_xor_sync(0xffffffffu, mx, 1, 8));
            mx = fmaxf(mx, __shfl_xor_sync(0xffffffffu, mx, 2, 8));
            mx = fmaxf(mx, __shfl_xor_sync(0xffffffffu, mx, 4, 8));
            float nm = fmaxf(mrow[i], mx);
            float corr = __expf(mrow[i] - nm);
            mrow[i] = nm;
            float ss = 0.f;
#pragma unroll
            for (int j = 0; j < 8; j++) { float p = __expf(sv[i][j] - nm); sv[i][j] = p; ss += p; }
            ss += __shfl_xor_sync(0xffffffffu, ss, 1, 8);
            ss += __shfl_xor_sync(0xffffffffu, ss, 2, 8);
            ss += __shfl_xor_sync(0xffffffffu, ss, 4, 8);
            lrow[i] = lrow[i] * corr + ss;
            ull c2 = pk2(corr, corr);
#pragma unroll
            for (int j = 0; j < 4; j++) o[i][j] = f2mul(o[i][j], c2);
        }

        for (int sl = 0; sl < 8; sl++) {
#pragma unroll
            for (int j = 0; j < 8; j++) {
                const int kl = sl * 8 + j;
                ulonglong2 v01 = *(const ulonglong2*)&Vs[kl * VPAD + n0];
                ulonglong2 v23 = *(const ulonglong2*)&Vs[kl * VPAD + n0 + 4];
#pragma unroll
                for (int i = 0; i < 4; i++) {
                    float p = __shfl_sync(0xffffffffu, sv[i][j], sl, 8);
                    ull p2 = pk2(p, p);
                    o[i][0] = f2fma(p2, v01.x, o[i][0]);
                    o[i][1] = f2fma(p2, v01.y, o[i][1]);
                    o[i][2] = f2fma(p2, v23.x, o[i][2]);
                    o[i][3] = f2fma(p2, v23.y, o[i][3]);
                }
            }
        }
    }

#pragma unroll
    for (int i = 0; i < 4; i++) {
        float inv = 1.0f / lrow[i];
        ull iv = pk2(inv, inv);
        float2 a = up2(f2mul(o[i][0], iv)), b2 = up2(f2mul(o[i][1], iv));
        float2 c = up2(f2mul(o[i][2], iv)), d2 = up2(f2mul(o[i][3], iv));
        float* op = Op + headOff + (size_t)(qBase + m0 + i) * D_ + n0;
        *(float4*)op       = make_float4(a.x, a.y, b2.x, b2.y);
        *(float4*)(op + 4) = make_float4(c.x, c.y, d2.x, d2.y);
    }
}

// ---------------------------------------------------------------------------
extern "C" void kernel_launch(void* const* d_in, const int* in_sizes, int n_in,
                              void* d_out, int out_size)
{
    const float* Q  = (const float*)d_in[0];
    const float* Kx = (const float*)d_in[1];
    const float* Vx = (const float*)d_in[2];
    const float* Wq = (const float*)d_in[3];
    const float* Wk = (const float*)d_in[4];
    const float* Wv = (const float*)d_in[5];
    const float* Wo = (const float*)d_in[6];
    float* out = (float*)d_out;

    float *q, *k, *v, *o;
    cudaGetSymbolAddress((void**)&q, g_q);
    cudaGetSymbolAddress((void**)&k, g_k);
    cudaGetSymbolAddress((void**)&v, g_v);
    cudaGetSymbolAddress((void**)&o, g_o);

    const int flashSmem = (64 * 128 + 64 * 64 + 64 * VPAD) * sizeof(float); // 66560
    cudaFuncSetAttribute(flash_v2, cudaFuncAttributeMaxDynamicSharedMemorySize, flashSmem);

    gemm128<<<dim3(8, 64, 3), 256>>>(Q, Kx, Vx, Wq, Wk, Wv, q, k, v);
    flash_v2<<<dim3(S_ / 128, B_ * H_), 256, flashSmem>>>(q, k, v, o);
    gemm128<<<dim3(8, 64, 1), 256>>>(o, o, o, Wo, Wo, Wo, out, out, out);
}

// round 11
// speedup vs baseline: 1.8142x; 1.8142x over previous
#include <cuda_runtime.h>
#include <cstdint>
#include <math.h>

#define B_  4
#define S_  2048
#define D_  1024
#define H_  16
#define DH_ 64
#define MROWS (B_ * S_)
#define VPAD 68

typedef unsigned long long ull;

__device__ __forceinline__ ull pk2(float a, float b) {
    ull r; asm("mov.b64 %0, {%1, %2};" : "=l"(r) : "f"(a), "f"(b)); return r;
}
__device__ __forceinline__ float2 up2(ull v) {
    float2 r; asm("mov.b64 {%0, %1}, %2;" : "=f"(r.x), "=f"(r.y) : "l"(v)); return r;
}
__device__ __forceinline__ ull f2fma(ull a, ull b, ull c) {
    ull d; asm("fma.rn.f32x2 %0, %1, %2, %3;" : "=l"(d) : "l"(a), "l"(b), "l"(c)); return d;
}
__device__ __forceinline__ ull f2mul(ull a, ull b) {
    ull d; asm("mul.rn.f32x2 %0, %1, %2;" : "=l"(d) : "l"(a), "l"(b)); return d;
}

__device__ float g_q[MROWS * D_];
__device__ float g_k[MROWS * D_];
__device__ float g_v[MROWS * D_];
__device__ float g_o[MROWS * D_];

// ---------------------------------------------------------------------------
// GEMM v4: C[8192,1024] = A * W^T.  128x128 tile, BK=16, 256 threads.
// Per-thread 16m x 4n with accumulators PACKED ALONG M:
//   - A read as natural pairs (4 broadcast LDS.128/k, zero MOVs)
//   - B: 1 LDS.128/k (conflict-free: n0=4*nq tiles banks) + 4 dup MOVs
//   - 41 issues per 32 FFMA2 -> 78% fma ceiling
// Double-buffered smem + register prefetch; ~116 regs -> no spill at 128 cap.
// ---------------------------------------------------------------------------
__global__ __launch_bounds__(256, 2) void gemm128(
    const float* __restrict__ A0, const float* __restrict__ A1, const float* __restrict__ A2,
    const float* __restrict__ W0, const float* __restrict__ W1, const float* __restrict__ W2,
    float* __restrict__ C0, float* __restrict__ C1, float* __restrict__ C2)
{
    const float* A; const float* W; float* C;
    if (blockIdx.z == 0)      { A = A0; W = W0; C = C0; }
    else if (blockIdx.z == 1) { A = A1; W = W1; C = C1; }
    else                      { A = A2; W = W2; C = C2; }

    __shared__ __align__(16) float As[2][16][128];   // 16 KB
    __shared__ __align__(16) float Bs[2][16][128];   // 16 KB

    const int tid = threadIdx.x;
    const int m0  = (tid >> 5) << 4;     // 0..112 (warp-uniform -> A broadcast)
    const int n0  = (tid & 31) << 2;     // 0..124 (bank-tiling B reads)
    const size_t mBase = (size_t)blockIdx.y * 128;
    const size_t nBase = (size_t)blockIdx.x * 128;

    const int lrow = tid >> 1;           // 0..127
    const int lkq  = (tid & 1) << 3;     // 0 or 8

    const float* aG = A + (mBase + lrow) * D_ + lkq;
    const float* wG = W + (nBase + lrow) * D_ + lkq;

    float4 pa0 = *(const float4*)aG, pa1 = *(const float4*)(aG + 4);
    float4 pb0 = *(const float4*)wG, pb1 = *(const float4*)(wG + 4);

    ull acc[8][4];                       // [m-pair][n]
#pragma unroll
    for (int i = 0; i < 8; i++)
#pragma unroll
        for (int j = 0; j < 4; j++) acc[i][j] = 0ULL;

#define STORE_STAGE(s)                                                        \
    {                                                                         \
        As[s][lkq + 0][lrow] = pa0.x;  As[s][lkq + 1][lrow] = pa0.y;          \
        As[s][lkq + 2][lrow] = pa0.z;  As[s][lkq + 3][lrow] = pa0.w;          \
        As[s][lkq + 4][lrow] = pa1.x;  As[s][lkq + 5][lrow] = pa1.y;          \
        As[s][lkq + 6][lrow] = pa1.z;  As[s][lkq + 7][lrow] = pa1.w;          \
        Bs[s][lkq + 0][lrow] = pb0.x;  Bs[s][lkq + 1][lrow] = pb0.y;          \
        Bs[s][lkq + 2][lrow] = pb0.z;  Bs[s][lkq + 3][lrow] = pb0.w;          \
        Bs[s][lkq + 4][lrow] = pb1.x;  Bs[s][lkq + 5][lrow] = pb1.y;          \
        Bs[s][lkq + 6][lrow] = pb1.z;  Bs[s][lkq + 7][lrow] = pb1.w;          \
    }

    STORE_STAGE(0);
    aG += 16; wG += 16;
    pa0 = *(const float4*)aG;  pa1 = *(const float4*)(aG + 4);
    pb0 = *(const float4*)wG;  pb1 = *(const float4*)(wG + 4);
    __syncthreads();

    const int NT = D_ / 16;              // 64
    for (int t = 0; t < NT; t++) {
        const int cur = t & 1;
#pragma unroll
        for (int k = 0; k < 16; k++) {
            // A: natural pairs (m0 warp-uniform -> full broadcast, 1 wf each)
            ulonglong2 a01 = *(const ulonglong2*)&As[cur][k][m0];
            ulonglong2 a23 = *(const ulonglong2*)&As[cur][k][m0 + 4];
            ulonglong2 a45 = *(const ulonglong2*)&As[cur][k][m0 + 8];
            ulonglong2 a67 = *(const ulonglong2*)&As[cur][k][m0 + 12];
            // B: 4 floats, 16B*nq addresses -> perfect bank tiling (4 wf)
            float4 bv = *(const float4*)&Bs[cur][k][n0];
            ull b0 = pk2(bv.x, bv.x), b1 = pk2(bv.y, bv.y);
            ull b2 = pk2(bv.z, bv.z), b3 = pk2(bv.w, bv.w);
            acc[0][0] = f2fma(a01.x, b0, acc[0][0]);
            acc[0][1] = f2fma(a01.x, b1, acc[0][1]);
            acc[0][2] = f2fma(a01.x, b2, acc[0][2]);
            acc[0][3] = f2fma(a01.x, b3, acc[0][3]);
            acc[1][0] = f2fma(a01.y, b0, acc[1][0]);
            acc[1][1] = f2fma(a01.y, b1, acc[1][1]);
            acc[1][2] = f2fma(a01.y, b2, acc[1][2]);
            acc[1][3] = f2fma(a01.y, b3, acc[1][3]);
            acc[2][0] = f2fma(a23.x, b0, acc[2][0]);
            acc[2][1] = f2fma(a23.x, b1, acc[2][1]);
            acc[2][2] = f2fma(a23.x, b2, acc[2][2]);
            acc[2][3] = f2fma(a23.x, b3, acc[2][3]);
            acc[3][0] = f2fma(a23.y, b0, acc[3][0]);
            acc[3][1] = f2fma(a23.y, b1, acc[3][1]);
            acc[3][2] = f2fma(a23.y, b2, acc[3][2]);
            acc[3][3] = f2fma(a23.y, b3, acc[3][3]);
            acc[4][0] = f2fma(a45.x, b0, acc[4][0]);
            acc[4][1] = f2fma(a45.x, b1, acc[4][1]);
            acc[4][2] = f2fma(a45.x, b2, acc[4][2]);
            acc[4][3] = f2fma(a45.x, b3, acc[4][3]);
            acc[5][0] = f2fma(a45.y, b0, acc[5][0]);
            acc[5][1] = f2fma(a45.y, b1, acc[5][1]);
            acc[5][2] = f2fma(a45.y, b2, acc[5][2]);
            acc[5][3] = f2fma(a45.y, b3, acc[5][3]);
            acc[6][0] = f2fma(a67.x, b0, acc[6][0]);
            acc[6][1] = f2fma(a67.x, b1, acc[6][1]);
            acc[6][2] = f2fma(a67.x, b2, acc[6][2]);
            acc[6][3] = f2fma(a67.x, b3, acc[6][3]);
            acc[7][0] = f2fma(a67.y, b0, acc[7][0]);
            acc[7][1] = f2fma(a67.y, b1, acc[7][1]);
            acc[7][2] = f2fma(a67.y, b2, acc[7][2]);
            acc[7][3] = f2fma(a67.y, b3, acc[7][3]);
        }
        if (t < NT - 1) {
            STORE_STAGE(cur ^ 1);
            if (t < NT - 2) {
                aG += 16; wG += 16;
                pa0 = *(const float4*)aG;  pa1 = *(const float4*)(aG + 4);
                pb0 = *(const float4*)wG;  pb1 = *(const float4*)(wG + 4);
            }
        }
        __syncthreads();
    }
#undef STORE_STAGE

    // epilogue: pair p covers rows m0+2p, m0+2p+1; cols n0..n0+3 contiguous
#pragma unroll
    for (int p = 0; p < 8; p++) {
        float2 c0 = up2(acc[p][0]), c1 = up2(acc[p][1]);
        float2 c2 = up2(acc[p][2]), c3 = up2(acc[p][3]);
        float* r0 = C + (mBase + m0 + 2 * p) * D_ + nBase + n0;
        *(float4*)r0        = make_float4(c0.x, c1.x, c2.x, c3.x);
        *(float4*)(r0 + D_) = make_float4(c0.y, c1.y, c2.y, c3.y);
    }
}

// ---------------------------------------------------------------------------
// Flash v2 (unchanged): 256 threads, 4q x 8k tile, shfl softmax.
// ---------------------------------------------------------------------------
__global__ __launch_bounds__(256, 2) void flash_v2(
    const float* __restrict__ Qp, const float* __restrict__ Kp,
    const float* __restrict__ Vp, float* __restrict__ Op)
{
    extern __shared__ __align__(16) char smr[];
    float* Qs = (float*)smr;            // 64*128
    float* Ks = Qs + 64 * 128;          // 64*64
    float* Vs = Ks + 64 * 64;           // 64*VPAD

    const int tid = threadIdx.x;
    const int n0  = (tid & 7) << 3;
    const int m0  = (tid >> 3) << 2;
    const int bx  = gridDim.x - 1 - blockIdx.x;
    const int qBase = bx * 128;
    const int b = blockIdx.y >> 4, h = blockIdx.y & 15;
    const size_t headOff = (size_t)b * S_ * D_ + (size_t)h * DH_;

    {
        int qr = tid >> 1, dh = (tid & 1) * 32;
        const float* qs = Qp + headOff + (size_t)(qBase + qr) * D_ + dh;
#pragma unroll
        for (int c = 0; c < 8; c++) {
            float4 v = *(const float4*)(qs + 4 * c);
            Qs[(dh + 4*c + 0) * 128 + qr] = v.x * 0.125f;
            Qs[(dh + 4*c + 1) * 128 + qr] = v.y * 0.125f;
            Qs[(dh + 4*c + 2) * 128 + qr] = v.z * 0.125f;
            Qs[(dh + 4*c + 3) * 128 + qr] = v.w * 0.125f;
        }
    }

    ull o[4][4];
#pragma unroll
    for (int i = 0; i < 4; i++)
#pragma unroll
        for (int j = 0; j < 4; j++) o[i][j] = 0ULL;
    float mrow[4] = {-INFINITY, -INFINITY, -INFINITY, -INFINITY};
    float lrow[4] = {0.f, 0.f, 0.f, 0.f};

    const int kr = tid >> 2, dq = (tid & 3) << 4;
    const int nkt = 2 * bx + 2;

    for (int kt = 0; kt < nkt; kt++) {
        const float* kp = Kp + headOff + (size_t)(kt * 64 + kr) * D_ + dq;
        const float* vp = Vp + headOff + (size_t)(kt * 64 + kr) * D_ + dq;
        float4 kv[4], vv[4];
#pragma unroll
        for (int c = 0; c < 4; c++) { kv[c] = *(const float4*)(kp + 4*c); vv[c] = *(const float4*)(vp + 4*c); }
        __syncthreads();
#pragma unroll
        for (int c = 0; c < 4; c++) {
            Ks[(dq + 4*c + 0) * 64 + kr] = kv[c].x;
            Ks[(dq + 4*c + 1) * 64 + kr] = kv[c].y;
            Ks[(dq + 4*c + 2) * 64 + kr] = kv[c].z;
            Ks[(dq + 4*c + 3) * 64 + kr] = kv[c].w;
            *(float4*)&Vs[kr * VPAD + dq + 4*c] = vv[c];
        }
        __syncthreads();

        ull s2[4][4];
#pragma unroll
        for (int i = 0; i < 4; i++)
#pragma unroll
            for (int j = 0; j < 4; j++) s2[i][j] = 0ULL;
        for (int d8 = 0; d8 < 8; d8++) {
#pragma unroll
            for (int dd = 0; dd < 8; dd++) {
                const int d = d8 * 8 + dd;
                float4 qv = *(const float4*)&Qs[d * 128 + m0];
                ulonglong2 k01 = *(const ulonglong2*)&Ks[d * 64 + n0];
                ulonglong2 k23 = *(const ulonglong2*)&Ks[d * 64 + n0 + 4];
                float qa[4] = {qv.x, qv.y, qv.z, qv.w};
#pragma unroll
                for (int i = 0; i < 4; i++) {
                    ull q2 = pk2(qa[i], qa[i]);
                    s2[i][0] = f2fma(q2, k01.x, s2[i][0]);
                    s2[i][1] = f2fma(q2, k01.y, s2[i][1]);
                    s2[i][2] = f2fma(q2, k23.x, s2[i][2]);
                    s2[i][3] = f2fma(q2, k23.y, s2[i][3]);
                }
            }
        }

        float sv[4][8];
        const bool bnd = (kt >= nkt - 2);
        const int kOff = kt * 64 + n0;
#pragma unroll
        for (int i = 0; i < 4; i++) {
#pragma unroll
            for (int j2 = 0; j2 < 4; j2++) {
                float2 u = up2(s2[i][j2]);
                sv[i][2*j2] = u.x; sv[i][2*j2+1] = u.y;
            }
            if (bnd) {
                int q = qBase + m0 + i;
#pragma unroll
                for (int j = 0; j < 8; j++)
                    if (kOff + j > q) sv[i][j] = -INFINITY;
            }
            float mx = sv[i][0];
#pragma unroll
            for (int j = 1; j < 8; j++) mx = fmaxf(mx, sv[i][j]);
            mx = fmaxf(mx, __shfl_xor_sync(0xffffffffu, mx, 1, 8));
            mx = fmaxf(mx, __shfl_xor_sync(0xffffffffu, mx, 2, 8));
            mx = fmaxf(mx, __shfl_xor_sync(0xffffffffu, mx, 4, 8));
            float nm = fmaxf(mrow[i], mx);
            float corr = __expf(mrow[i] - nm);
            mrow[i] = nm;
            float ss = 0.f;
#pragma unroll
            for (int j = 0; j < 8; j++) { float p = __expf(sv[i][j] - nm); sv[i][j] = p; ss += p; }
            ss += __shfl_xor_sync(0xffffffffu, ss, 1, 8);
            ss += __shfl_xor_sync(0xffffffffu, ss, 2, 8);
            ss += __shfl_xor_sync(0xffffffffu, ss, 4, 8);
            lrow[i] = lrow[i] * corr + ss;
            ull c2 = pk2(corr, corr);
#pragma unroll
            for (int j = 0; j < 4; j++) o[i][j] = f2mul(o[i][j], c2);
        }

        for (int sl = 0; sl < 8; sl++) {
#pragma unroll
            for (int j = 0; j < 8; j++) {
                const int kl = sl * 8 + j;
                ulonglong2 v01 = *(const ulonglong2*)&Vs[kl * VPAD + n0];
                ulonglong2 v23 = *(const ulonglong2*)&Vs[kl * VPAD + n0 + 4];
#pragma unroll
                for (int i = 0; i < 4; i++) {
                    float p = __shfl_sync(0xffffffffu, sv[i][j], sl, 8);
                    ull p2 = pk2(p, p);
                    o[i][0] = f2fma(p2, v01.x, o[i][0]);
                    o[i][1] = f2fma(p2, v01.y, o[i][1]);
                    o[i][2] = f2fma(p2, v23.x, o[i][2]);
                    o[i][3] = f2fma(p2, v23.y, o[i][3]);
                }
            }
        }
    }

#pragma unroll
    for (int i = 0; i < 4; i++) {
        float inv = 1.0f / lrow[i];
        ull iv = pk2(inv, inv);
        float2 a = up2(f2mul(o[i][0], iv)), b2 = up2(f2mul(o[i][1], iv));
        float2 c = up2(f2mul(o[i][2], iv)), d2 = up2(f2mul(o[i][3], iv));
        float* op = Op + headOff + (size_t)(qBase + m0 + i) * D_ + n0;
        *(float4*)op       = make_float4(a.x, a.y, b2.x, b2.y);
        *(float4*)(op + 4) = make_float4(c.x, c.y, d2.x, d2.y);
    }
}

// ---------------------------------------------------------------------------
extern "C" void kernel_launch(void* const* d_in, const int* in_sizes, int n_in,
                              void* d_out, int out_size)
{
    const float* Q  = (const float*)d_in[0];
    const float* Kx = (const float*)d_in[1];
    const float* Vx = (const float*)d_in[2];
    const float* Wq = (const float*)d_in[3];
    const float* Wk = (const float*)d_in[4];
    const float* Wv = (const float*)d_in[5];
    const float* Wo = (const float*)d_in[6];
    float* out = (float*)d_out;

    float *q, *k, *v, *o;
    cudaGetSymbolAddress((void**)&q, g_q);
    cudaGetSymbolAddress((void**)&k, g_k);
    cudaGetSymbolAddress((void**)&v, g_v);
    cudaGetSymbolAddress((void**)&o, g_o);

    const int flashSmem = (64 * 128 + 64 * 64 + 64 * VPAD) * sizeof(float); // 66560
    cudaFuncSetAttribute(flash_v2, cudaFuncAttributeMaxDynamicSharedMemorySize, flashSmem);

    gemm128<<<dim3(8, 64, 3), 256>>>(Q, Kx, Vx, Wq, Wk, Wv, q, k, v);
    flash_v2<<<dim3(S_ / 128, B_ * H_), 256, flashSmem>>>(q, k, v, o);
    gemm128<<<dim3(8, 64, 1), 256>>>(o, o, o, Wo, Wo, Wo, out, out, out);
}

// round 13
// speedup vs baseline: 1.8278x; 1.0075x over previous
#include <cuda_runtime.h>
#include <cstdint>
#include <math.h>

#define B_  4
#define S_  2048
#define D_  1024
#define H_  16
#define DH_ 64
#define MROWS (B_ * S_)
#define VPAD 68
#define PPAD 68

typedef unsigned long long ull;

__device__ __forceinline__ ull pk2(float a, float b) {
    ull r; asm("mov.b64 %0, {%1, %2};" : "=l"(r) : "f"(a), "f"(b)); return r;
}
__device__ __forceinline__ float2 up2(ull v) {
    float2 r; asm("mov.b64 {%0, %1}, %2;" : "=f"(r.x), "=f"(r.y) : "l"(v)); return r;
}
__device__ __forceinline__ ull f2fma(ull a, ull b, ull c) {
    ull d; asm("fma.rn.f32x2 %0, %1, %2, %3;" : "=l"(d) : "l"(a), "l"(b), "l"(c)); return d;
}
__device__ __forceinline__ ull f2mul(ull a, ull b) {
    ull d; asm("mul.rn.f32x2 %0, %1, %2;" : "=l"(d) : "l"(a), "l"(b)); return d;
}

__device__ float g_q[MROWS * D_];
__device__ float g_k[MROWS * D_];
__device__ float g_v[MROWS * D_];
__device__ float g_o[MROWS * D_];

// ---------------------------------------------------------------------------
// GEMM v4 (unchanged from R11 — 66% fma, 76% of f32x2 roof).
// ---------------------------------------------------------------------------
__global__ __launch_bounds__(256, 2) void gemm128(
    const float* __restrict__ A0, const float* __restrict__ A1, const float* __restrict__ A2,
    const float* __restrict__ W0, const float* __restrict__ W1, const float* __restrict__ W2,
    float* __restrict__ C0, float* __restrict__ C1, float* __restrict__ C2)
{
    const float* A; const float* W; float* C;
    if (blockIdx.z == 0)      { A = A0; W = W0; C = C0; }
    else if (blockIdx.z == 1) { A = A1; W = W1; C = C1; }
    else                      { A = A2; W = W2; C = C2; }

    __shared__ __align__(16) float As[2][16][128];
    __shared__ __align__(16) float Bs[2][16][128];

    const int tid = threadIdx.x;
    const int m0  = (tid >> 5) << 4;
    const int n0  = (tid & 31) << 2;
    const size_t mBase = (size_t)blockIdx.y * 128;
    const size_t nBase = (size_t)blockIdx.x * 128;

    const int lrow = tid >> 1;
    const int lkq  = (tid & 1) << 3;

    const float* aG = A + (mBase + lrow) * D_ + lkq;
    const float* wG = W + (nBase + lrow) * D_ + lkq;

    float4 pa0 = *(const float4*)aG, pa1 = *(const float4*)(aG + 4);
    float4 pb0 = *(const float4*)wG, pb1 = *(const float4*)(wG + 4);

    ull acc[8][4];
#pragma unroll
    for (int i = 0; i < 8; i++)
#pragma unroll
        for (int j = 0; j < 4; j++) acc[i][j] = 0ULL;

#define STORE_STAGE(s)                                                        \
    {                                                                         \
        As[s][lkq + 0][lrow] = pa0.x;  As[s][lkq + 1][lrow] = pa0.y;          \
        As[s][lkq + 2][lrow] = pa0.z;  As[s][lkq + 3][lrow] = pa0.w;          \
        As[s][lkq + 4][lrow] = pa1.x;  As[s][lkq + 5][lrow] = pa1.y;          \
        As[s][lkq + 6][lrow] = pa1.z;  As[s][lkq + 7][lrow] = pa1.w;          \
        Bs[s][lkq + 0][lrow] = pb0.x;  Bs[s][lkq + 1][lrow] = pb0.y;          \
        Bs[s][lkq + 2][lrow] = pb0.z;  Bs[s][lkq + 3][lrow] = pb0.w;          \
        Bs[s][lkq + 4][lrow] = pb1.x;  Bs[s][lkq + 5][lrow] = pb1.y;          \
        Bs[s][lkq + 6][lrow] = pb1.z;  Bs[s][lkq + 7][lrow] = pb1.w;          \
    }

    STORE_STAGE(0);
    aG += 16; wG += 16;
    pa0 = *(const float4*)aG;  pa1 = *(const float4*)(aG + 4);
    pb0 = *(const float4*)wG;  pb1 = *(const float4*)(wG + 4);
    __syncthreads();

    const int NT = D_ / 16;
    for (int t = 0; t < NT; t++) {
        const int cur = t & 1;
#pragma unroll
        for (int k = 0; k < 16; k++) {
            ulonglong2 a01 = *(const ulonglong2*)&As[cur][k][m0];
            ulonglong2 a23 = *(const ulonglong2*)&As[cur][k][m0 + 4];
            ulonglong2 a45 = *(const ulonglong2*)&As[cur][k][m0 + 8];
            ulonglong2 a67 = *(const ulonglong2*)&As[cur][k][m0 + 12];
            float4 bv = *(const float4*)&Bs[cur][k][n0];
            ull b0 = pk2(bv.x, bv.x), b1 = pk2(bv.y, bv.y);
            ull b2 = pk2(bv.z, bv.z), b3 = pk2(bv.w, bv.w);
            acc[0][0] = f2fma(a01.x, b0, acc[0][0]);
            acc[0][1] = f2fma(a01.x, b1, acc[0][1]);
            acc[0][2] = f2fma(a01.x, b2, acc[0][2]);
            acc[0][3] = f2fma(a01.x, b3, acc[0][3]);
            acc[1][0] = f2fma(a01.y, b0, acc[1][0]);
            acc[1][1] = f2fma(a01.y, b1, acc[1][1]);
            acc[1][2] = f2fma(a01.y, b2, acc[1][2]);
            acc[1][3] = f2fma(a01.y, b3, acc[1][3]);
            acc[2][0] = f2fma(a23.x, b0, acc[2][0]);
            acc[2][1] = f2fma(a23.x, b1, acc[2][1]);
            acc[2][2] = f2fma(a23.x, b2, acc[2][2]);
            acc[2][3] = f2fma(a23.x, b3, acc[2][3]);
            acc[3][0] = f2fma(a23.y, b0, acc[3][0]);
            acc[3][1] = f2fma(a23.y, b1, acc[3][1]);
            acc[3][2] = f2fma(a23.y, b2, acc[3][2]);
            acc[3][3] = f2fma(a23.y, b3, acc[3][3]);
            acc[4][0] = f2fma(a45.x, b0, acc[4][0]);
            acc[4][1] = f2fma(a45.x, b1, acc[4][1]);
            acc[4][2] = f2fma(a45.x, b2, acc[4][2]);
            acc[4][3] = f2fma(a45.x, b3, acc[4][3]);
            acc[5][0] = f2fma(a45.y, b0, acc[5][0]);
            acc[5][1] = f2fma(a45.y, b1, acc[5][1]);
            acc[5][2] = f2fma(a45.y, b2, acc[5][2]);
            acc[5][3] = f2fma(a45.y, b3, acc[5][3]);
            acc[6][0] = f2fma(a67.x, b0, acc[6][0]);
            acc[6][1] = f2fma(a67.x, b1, acc[6][1]);
            acc[6][2] = f2fma(a67.x, b2, acc[6][2]);
            acc[6][3] = f2fma(a67.x, b3, acc[6][3]);
            acc[7][0] = f2fma(a67.y, b0, acc[7][0]);
            acc[7][1] = f2fma(a67.y, b1, acc[7][1]);
            acc[7][2] = f2fma(a67.y, b2, acc[7][2]);
            acc[7][3] = f2fma(a67.y, b3, acc[7][3]);
        }
        if (t < NT - 1) {
            STORE_STAGE(cur ^ 1);
            if (t < NT - 2) {
                aG += 16; wG += 16;
                pa0 = *(const float4*)aG;  pa1 = *(const float4*)(aG + 4);
                pb0 = *(const float4*)wG;  pb1 = *(const float4*)(wG + 4);
            }
        }
        __syncthreads();
    }
#undef STORE_STAGE

#pragma unroll
    for (int p = 0; p < 8; p++) {
        float2 c0 = up2(acc[p][0]), c1 = up2(acc[p][1]);
        float2 c2 = up2(acc[p][2]), c3 = up2(acc[p][3]);
        float* r0 = C + (mBase + m0 + 2 * p) * D_ + nBase + n0;
        *(float4*)r0        = make_float4(c0.x, c1.x, c2.x, c3.x);
        *(float4*)(r0 + D_) = make_float4(c0.y, c1.y, c2.y, c3.y);
    }
}

// ---------------------------------------------------------------------------
// Flash v3: P routed through smem (no shfl in PV chains).
// 256 threads, q-block 128, k-block 64, thread tile 4q x 8{k,d}.
// Per tile: S=QK^T (reg GEMM) -> softmax -> P to Ps[128][PPAD] -> barrier ->
// PV as LDS-fed reg GEMM. K/V loads for kt+1 issued before PV (hidden).
// smem: Qs 32K + Ks 16K + Vs 17K + Ps 34K = 99.3 KB -> 2 CTA/SM.
// ---------------------------------------------------------------------------
__global__ __launch_bounds__(256, 2) void flash_v3(
    const float* __restrict__ Qp, const float* __restrict__ Kp,
    const float* __restrict__ Vp, float* __restrict__ Op)
{
    extern __shared__ __align__(16) char smr[];
    float* Qs = (float*)smr;            // [64 d][128 q]
    float* Ks = Qs + 64 * 128;          // [64 d][64 k]
    float* Vs = Ks + 64 * 64;           // [64 k][VPAD d]
    float* Ps = Vs + 64 * VPAD;         // [128 q][PPAD k]

    const int tid = threadIdx.x;
    const int n0  = (tid & 7) << 3;
    const int m0  = (tid >> 3) << 2;
    const int bx  = gridDim.x - 1 - blockIdx.x;   // heavy blocks first
    const int qBase = bx * 128;
    const int b = blockIdx.y >> 4, h = blockIdx.y & 15;
    const size_t headOff = (size_t)b * S_ * D_ + (size_t)h * DH_;

    {   // Q -> smem d-major, prescaled
        int qr = tid >> 1, dh = (tid & 1) * 32;
        const float* qs = Qp + headOff + (size_t)(qBase + qr) * D_ + dh;
#pragma unroll
        for (int c = 0; c < 8; c++) {
            float4 v = *(const float4*)(qs + 4 * c);
            Qs[(dh + 4*c + 0) * 128 + qr] = v.x * 0.125f;
            Qs[(dh + 4*c + 1) * 128 + qr] = v.y * 0.125f;
            Qs[(dh + 4*c + 2) * 128 + qr] = v.z * 0.125f;
            Qs[(dh + 4*c + 3) * 128 + qr] = v.w * 0.125f;
        }
    }

    ull o[4][4];
#pragma unroll
    for (int i = 0; i < 4; i++)
#pragma unroll
        for (int j = 0; j < 4; j++) o[i][j] = 0ULL;
    float mrow[4] = {-INFINITY, -INFINITY, -INFINITY, -INFINITY};
    float lrow[4] = {0.f, 0.f, 0.f, 0.f};

    const int kr = tid >> 2, dq = (tid & 3) << 4;
    const int nkt = 2 * bx + 2;
    const float* kBase = Kp + headOff + (size_t)kr * D_ + dq;
    const float* vBase = Vp + headOff + (size_t)kr * D_ + dq;

    // prologue: load tile 0
    float4 kv[4], vv[4];
#pragma unroll
    for (int c = 0; c < 4; c++) {
        kv[c] = *(const float4*)(kBase + 4*c);
        vv[c] = *(const float4*)(vBase + 4*c);
    }

    for (int kt = 0; kt < nkt; kt++) {
        __syncthreads();                 // prev tile fully consumed (incl. Ps)
#pragma unroll
        for (int c = 0; c < 4; c++) {
            Ks[(dq + 4*c + 0) * 64 + kr] = kv[c].x;
            Ks[(dq + 4*c + 1) * 64 + kr] = kv[c].y;
            Ks[(dq + 4*c + 2) * 64 + kr] = kv[c].z;
            Ks[(dq + 4*c + 3) * 64 + kr] = kv[c].w;
            *(float4*)&Vs[kr * VPAD + dq + 4*c] = vv[c];
        }
        __syncthreads();

        // ---- S = Q K^T ----
        ull s2[4][4];
#pragma unroll
        for (int i = 0; i < 4; i++)
#pragma unroll
            for (int j = 0; j < 4; j++) s2[i][j] = 0ULL;
        for (int d8 = 0; d8 < 8; d8++) {
#pragma unroll
            for (int dd = 0; dd < 8; dd++) {
                const int d = d8 * 8 + dd;
                float4 qv = *(const float4*)&Qs[d * 128 + m0];
                ulonglong2 k01 = *(const ulonglong2*)&Ks[d * 64 + n0];
                ulonglong2 k23 = *(const ulonglong2*)&Ks[d * 64 + n0 + 4];
                float qa[4] = {qv.x, qv.y, qv.z, qv.w};
#pragma unroll
                for (int i = 0; i < 4; i++) {
                    ull q2 = pk2(qa[i], qa[i]);
                    s2[i][0] = f2fma(q2, k01.x, s2[i][0]);
                    s2[i][1] = f2fma(q2, k01.y, s2[i][1]);
                    s2[i][2] = f2fma(q2, k23.x, s2[i][2]);
                    s2[i][3] = f2fma(q2, k23.y, s2[i][3]);
                }
            }
        }

        // ---- online softmax; write exp'd P to smem ----
        const bool bnd = (kt >= nkt - 2);
        const int kOff = kt * 64 + n0;
#pragma unroll
        for (int i = 0; i < 4; i++) {
            float sv[8];
#pragma unroll
            for (int j2 = 0; j2 < 4; j2++) {
                float2 u = up2(s2[i][j2]);
                sv[2*j2] = u.x; sv[2*j2+1] = u.y;
            }
            if (bnd) {
                int q = qBase + m0 + i;
#pragma unroll
                for (int j = 0; j < 8; j++)
                    if (kOff + j > q) sv[j] = -INFINITY;
            }
            float mx = sv[0];
#pragma unroll
            for (int j = 1; j < 8; j++) mx = fmaxf(mx, sv[j]);
            mx = fmaxf(mx, __shfl_xor_sync(0xffffffffu, mx, 1, 8));
            mx = fmaxf(mx, __shfl_xor_sync(0xffffffffu, mx, 2, 8));
            mx = fmaxf(mx, __shfl_xor_sync(0xffffffffu, mx, 4, 8));
            float nm = fmaxf(mrow[i], mx);
            float corr = __expf(mrow[i] - nm);
            mrow[i] = nm;
            float ss = 0.f;
#pragma unroll
            for (int j = 0; j < 8; j++) { float p = __expf(sv[j] - nm); sv[j] = p; ss += p; }
            ss += __shfl_xor_sync(0xffffffffu, ss, 1, 8);
            ss += __shfl_xor_sync(0xffffffffu, ss, 2, 8);
            ss += __shfl_xor_sync(0xffffffffu, ss, 4, 8);
            lrow[i] = lrow[i] * corr + ss;
            ull c2 = pk2(corr, corr);
#pragma unroll
            for (int j = 0; j < 4; j++) o[i][j] = f2mul(o[i][j], c2);
            // store P row chunk
            float* pr = &Ps[(m0 + i) * PPAD + n0];
            *(float4*)pr       = make_float4(sv[0], sv[1], sv[2], sv[3]);
            *(float4*)(pr + 4) = make_float4(sv[4], sv[5], sv[6], sv[7]);
        }

        // prefetch next K/V tile (hidden under PV)
        if (kt + 1 < nkt) {
            const float* kp = kBase + (size_t)(kt + 1) * 64 * D_;
            const float* vp = vBase + (size_t)(kt + 1) * 64 * D_;
#pragma unroll
            for (int c = 0; c < 4; c++) {
                kv[c] = *(const float4*)(kp + 4*c);
                vv[c] = *(const float4*)(vp + 4*c);
            }
        }
        __syncthreads();                 // Ps complete

        // ---- O += P V  (LDS-fed register GEMM, no shfl) ----
#pragma unroll 8
        for (int k = 0; k < 64; k++) {
            float p0 = Ps[(m0 + 0) * PPAD + k];
            float p1 = Ps[(m0 + 1) * PPAD + k];
            float p2 = Ps[(m0 + 2) * PPAD + k];
            float p3 = Ps[(m0 + 3) * PPAD + k];
            ulonglong2 v01 = *(const ulonglong2*)&Vs[k * VPAD + n0];
            ulonglong2 v23 = *(const ulonglong2*)&Vs[k * VPAD + n0 + 4];
            ull pp0 = pk2(p0, p0), pp1 = pk2(p1, p1);
            ull pp2 = pk2(p2, p2), pp3 = pk2(p3, p3);
            o[0][0] = f2fma(pp0, v01.x, o[0][0]);
            o[0][1] = f2fma(pp0, v01.y, o[0][1]);
            o[0][2] = f2fma(pp0, v23.x, o[0][2]);
            o[0][3] = f2fma(pp0, v23.y, o[0][3]);
            o[1][0] = f2fma(pp1, v01.x, o[1][0]);
            o[1][1] = f2fma(pp1, v01.y, o[1][1]);
            o[1][2] = f2fma(pp1, v23.x, o[1][2]);
            o[1][3] = f2fma(pp1, v23.y, o[1][3]);
            o[2][0] = f2fma(pp2, v01.x, o[2][0]);
            o[2][1] = f2fma(pp2, v01.y, o[2][1]);
            o[2][2] = f2fma(pp2, v23.x, o[2][2]);
            o[2][3] = f2fma(pp2, v23.y, o[2][3]);
            o[3][0] = f2fma(pp3, v01.x, o[3][0]);
            o[3][1] = f2fma(pp3, v01.y, o[3][1]);
            o[3][2] = f2fma(pp3, v23.x, o[3][2]);
            o[3][3] = f2fma(pp3, v23.y, o[3][3]);
        }
    }

#pragma unroll
    for (int i = 0; i < 4; i++) {
        float inv = 1.0f / lrow[i];
        ull iv = pk2(inv, inv);
        float2 a = up2(f2mul(o[i][0], iv)), b2 = up2(f2mul(o[i][1], iv));
        float2 c = up2(f2mul(o[i][2], iv)), d2 = up2(f2mul(o[i][3], iv));
        float* op = Op + headOff + (size_t)(qBase + m0 + i) * D_ + n0;
        *(float4*)op       = make_float4(a.x, a.y, b2.x, b2.y);
        *(float4*)(op + 4) = make_float4(c.x, c.y, d2.x, d2.y);
    }
}

// ---------------------------------------------------------------------------
extern "C" void kernel_launch(void* const* d_in, const int* in_sizes, int n_in,
                              void* d_out, int out_size)
{
    const float* Q  = (const float*)d_in[0];
    const float* Kx = (const float*)d_in[1];
    const float* Vx = (const float*)d_in[2];
    const float* Wq = (const float*)d_in[3];
    const float* Wk = (const float*)d_in[4];
    const float* Wv = (const float*)d_in[5];
    const float* Wo = (const float*)d_in[6];
    float* out = (float*)d_out;

    float *q, *k, *v, *o;
    cudaGetSymbolAddress((void**)&q, g_q);
    cudaGetSymbolAddress((void**)&k, g_k);
    cudaGetSymbolAddress((void**)&v, g_v);
    cudaGetSymbolAddress((void**)&o, g_o);

    const int flashSmem =
        (64 * 128 + 64 * 64 + 64 * VPAD + 128 * PPAD) * sizeof(float); // 101632
    cudaFuncSetAttribute(flash_v3, cudaFuncAttributeMaxDynamicSharedMemorySize, flashSmem);

    gemm128<<<dim3(8, 64, 3), 256>>>(Q, Kx, Vx, Wq, Wk, Wv, q, k, v);
    flash_v3<<<dim3(S_ / 128, B_ * H_), 256, flashSmem>>>(q, k, v, o);
    gemm128<<<dim3(8, 64, 1), 256>>>(o, o, o, Wo, Wo, Wo, out, out, out);
}